// round 12
// baseline (speedup 1.0000x reference)
#include <cuda_runtime.h>
#include <cuda_bf16.h>
#include <cooperative_groups.h>
namespace cg = cooperative_groups;

#define BB    64
#define LL    4096
#define DD    256
#define VOCAB 33
#define NT    512
#define NWARP 16
#define EPAD  264   // emb smem row stride (floats); 1056B rows keep float4 alignment
#define GRID  128   // phase A: 64 hist + 64 M1 ; phase B: 8 rowT x 16 colT

__device__ int   gcnt[BB][VOCAB];
__device__ float g_M1[VOCAB * DD];

__global__ __launch_bounds__(NT, 1)
void prot_net_coop(const int* __restrict__ X,
                   const int* __restrict__ vlen,
                   const float* __restrict__ emb,
                   const float* __restrict__ W1,
                   const float* __restrict__ b1,
                   const float* __restrict__ W2,
                   const float* __restrict__ b2,
                   float* __restrict__ out)
{
    // Typed overlay: phases are time-disjoint, separated by barriers.
    __shared__ union SMem {
        struct { int wh[NWARP][VOCAB]; } a;                       // hist
        struct {                                                   // M1 = emb@W1 tile
            float embs[VOCAB * EPAD];
            float w1t[4 * EPAD];
            float m1part[4][VOCAB][4];
        } m;
        struct {                                                   // phase B
            float  cnt[8][VOCAB];
            float  h[8][DD];
            float4 part[16][8][4];
        } b;
    } sm;

    const int bid = blockIdx.x;
    const int tid = threadIdx.x;

    // ================= PHASE A =================
    if (bid < 64) {
        // ---- full-row histogram ----
        const int warp = tid >> 5;
        const int row  = bid;
        const int4 xa = ((const int4*)X)[row * (LL / 4) + tid];
        const int4 xb = ((const int4*)X)[row * (LL / 4) + 512 + tid];
        const int  vl = vlen[row];
        const int  la = tid * 4;
        const int  lb = 2048 + tid * 4;

        for (int i = tid; i < NWARP * VOCAB; i += NT)
            (&sm.a.wh[0][0])[i] = 0;
        __syncthreads();

        if (la < vl) {
            atomicAdd(&sm.a.wh[warp][xa.x], 1);
            if (la + 1 < vl) atomicAdd(&sm.a.wh[warp][xa.y], 1);
            if (la + 2 < vl) atomicAdd(&sm.a.wh[warp][xa.z], 1);
            if (la + 3 < vl) atomicAdd(&sm.a.wh[warp][xa.w], 1);
        }
        if (lb < vl) {
            atomicAdd(&sm.a.wh[warp][xb.x], 1);
            if (lb + 1 < vl) atomicAdd(&sm.a.wh[warp][xb.y], 1);
            if (lb + 2 < vl) atomicAdd(&sm.a.wh[warp][xb.z], 1);
            if (lb + 3 < vl) atomicAdd(&sm.a.wh[warp][xb.w], 1);
        }
        __syncthreads();

        if (tid < VOCAB) {
            int s = 0;
            #pragma unroll
            for (int w = 0; w < NWARP; w++) s += sm.a.wh[w][tid];
            gcnt[row][tid] = s;
        }
        __syncthreads();               // quiesce overlay before phase B reuse
    } else {
        // ---- M1[:, c0..c0+3] = emb @ W1[:, c0..c0+3]  (W1 tile = 4 KB) ----
        const int c0 = (bid - 64) * 4;

        const float4* embv = (const float4*)emb;
        for (int i = tid; i < VOCAB * (DD / 4); i += NT) {
            const int v  = i >> 6;
            const int d4 = i & 63;
            *(float4*)&sm.m.embs[v * EPAD + d4 * 4] = embv[i];
        }
        if (tid < DD) {
            const float4 wr = ((const float4*)W1)[tid * (DD / 4) + (c0 >> 2)];
            sm.m.w1t[0 * EPAD + tid] = wr.x;
            sm.m.w1t[1 * EPAD + tid] = wr.y;
            sm.m.w1t[2 * EPAD + tid] = wr.z;
            sm.m.w1t[3 * EPAD + tid] = wr.w;
        }
        __syncthreads();

        const int c  = tid & 3;
        const int v  = (tid >> 2) & 31;
        const int kg = tid >> 7;                     // 0..3, 64 k each
        const float* ev  = sm.m.embs + v * EPAD + kg * 64;
        const float* e32 = sm.m.embs + 32 * EPAD + kg * 64;
        const float* wv  = sm.m.w1t + c * EPAD + kg * 64;

        float a = 0.f, a2 = 0.f;
        #pragma unroll
        for (int kk = 0; kk < 64; kk += 4) {
            const float4 e4 = *(const float4*)(ev + kk);
            const float4 w4 = *(const float4*)(wv + kk);
            a = fmaf(e4.x, w4.x, a);
            a = fmaf(e4.y, w4.y, a);
            a = fmaf(e4.z, w4.z, a);
            a = fmaf(e4.w, w4.w, a);
            if (v == 0) {                            // extra vocab row 32
                const float4 f4 = *(const float4*)(e32 + kk);
                a2 = fmaf(f4.x, w4.x, a2);
                a2 = fmaf(f4.y, w4.y, a2);
                a2 = fmaf(f4.z, w4.z, a2);
                a2 = fmaf(f4.w, w4.w, a2);
            }
        }
        __syncthreads();               // embs/w1t reads done before m1part writes (overlap-safe)
        sm.m.m1part[kg][v][c] = a;
        if (v == 0) sm.m.m1part[kg][32][c] = a2;
        __syncthreads();

        if (tid < VOCAB * 4) {
            const int v2 = tid >> 2, c2 = tid & 3;
            float s = 0.f;
            #pragma unroll
            for (int g = 0; g < 4; g++) s += sm.m.m1part[g][v2][c2];
            g_M1[v2 * DD + c0 + c2] = s;
        }
        __syncthreads();
    }

    // ================= GRID BARRIER (all blocks reach this; no early returns) ======
    cg::this_grid().sync();

    // ================= PHASE B: 8-row x 16-col output tiles =================
    {
        const int r0  = (bid >> 4) * 8;
        const int c0b = (bid & 15) * 16;

        if (tid < 8 * VOCAB) {
            const int r = tid / VOCAB, v = tid % VOCAB;
            sm.b.cnt[r][v] = (float)gcnt[r0 + r][v];
        }
        __syncthreads();

        // ---- stage 1: h for 8 rows; 33 independent coalesced LDGs/thread ----
        {
            const int d  = tid & 255;
            const int rh = tid >> 8;                 // 0/1 -> rows [4rh, 4rh+4)
            const float bb = b1[d];
            float a0 = 0.f, a1 = 0.f, a2 = 0.f, a3 = 0.f;
            #pragma unroll
            for (int v = 0; v < VOCAB; v++) {
                const float m = g_M1[v * DD + d];
                a0 = fmaf(sm.b.cnt[rh * 4 + 0][v], m, a0);
                a1 = fmaf(sm.b.cnt[rh * 4 + 1][v], m, a1);
                a2 = fmaf(sm.b.cnt[rh * 4 + 2][v], m, a2);
                a3 = fmaf(sm.b.cnt[rh * 4 + 3][v], m, a3);
            }
            sm.b.h[rh * 4 + 0][d] = fmaxf(a0 + bb, 0.f);
            sm.b.h[rh * 4 + 1][d] = fmaxf(a1 + bb, 0.f);
            sm.b.h[rh * 4 + 2][d] = fmaxf(a2 + bb, 0.f);
            sm.b.h[rh * 4 + 3][d] = fmaxf(a3 + bb, 0.f);
        }
        __syncthreads();

        // ---- stage 2: out tile = relu(h @ W2[:, c0b..+16) + b2); W2 reused 8x ----
        {
            const int kg   = tid >> 5;               // 0..15, 16 k each
            const int lane = tid & 31;
            const int rq   = lane >> 2;              // row 0..7
            const int c4   = lane & 3;               // float4 col
            const int cf4  = (c0b >> 2) + c4;
            const float4* W2v = (const float4*)W2;

            float4 acc = make_float4(0.f, 0.f, 0.f, 0.f);
            #pragma unroll
            for (int kk = 0; kk < 16; kk++) {
                const int k = kg * 16 + kk;
                const float4 w = W2v[k * (DD / 4) + cf4];  // 4 distinct/warp, L1-hot
                const float  s = sm.b.h[rq][k];
                acc.x = fmaf(s, w.x, acc.x);
                acc.y = fmaf(s, w.y, acc.y);
                acc.z = fmaf(s, w.z, acc.z);
                acc.w = fmaf(s, w.w, acc.w);
            }
            sm.b.part[kg][rq][c4] = acc;
        }
        __syncthreads();

        if (tid < 32) {
            const int r = tid >> 2, c4 = tid & 3;
            float4 s = make_float4(0.f, 0.f, 0.f, 0.f);
            #pragma unroll
            for (int kg = 0; kg < 16; kg++) {
                const float4 p = sm.b.part[kg][r][c4];
                s.x += p.x; s.y += p.y; s.z += p.z; s.w += p.w;
            }
            const float4 bb = ((const float4*)b2)[(c0b >> 2) + c4];
            s.x = fmaxf(s.x + bb.x, 0.f);
            s.y = fmaxf(s.y + bb.y, 0.f);
            s.z = fmaxf(s.z + bb.z, 0.f);
            s.w = fmaxf(s.w + bb.w, 0.f);
            *((float4*)&out[(r0 + r) * DD + c0b + c4 * 4]) = s;
        }
    }
}

extern "C" void kernel_launch(void* const* d_in, const int* in_sizes, int n_in,
                              void* d_out, int out_size)
{
    const int*   X    = (const int*)d_in[0];
    const int*   vlen = (const int*)d_in[1];
    const float* emb  = (const float*)d_in[2];
    const float* W1   = (const float*)d_in[3];
    const float* b1   = (const float*)d_in[4];
    const float* W2   = (const float*)d_in[5];
    const float* b2   = (const float*)d_in[6];
    float*       out  = (float*)d_out;

    void* args[] = { (void*)&X, (void*)&vlen, (void*)&emb, (void*)&W1,
                     (void*)&b1, (void*)&W2, (void*)&b2, (void*)&out };
    cudaLaunchCooperativeKernel((void*)prot_net_coop,
                                dim3(GRID), dim3(NT), args, 0, (cudaStream_t)0);
}

// round 13
// speedup vs baseline: 1.0847x; 1.0847x over previous
#include <cuda_runtime.h>
#include <cuda_bf16.h>
#include <cooperative_groups.h>
namespace cg = cooperative_groups;

#define BB    64
#define LL    4096
#define DD    256
#define VOCAB 33
#define NT    512
#define NWARP 16
#define GRID  128     // A: 64 rows x 2 halves ; C/D: 16 rowG x 8 colT

__device__ int   gpart[GRID][VOCAB];   // per-block half-row histograms (overwritten)
__device__ float g_h[BB * DD];         // layer-1 activations (overwritten)

__global__ __launch_bounds__(NT, 1)
void prot_net_coop(const int* __restrict__ X,
                   const int* __restrict__ vlen,
                   const float* __restrict__ emb,
                   const float* __restrict__ W1,
                   const float* __restrict__ b1,
                   const float* __restrict__ W2,
                   const float* __restrict__ b2,
                   float* __restrict__ out)
{
    __shared__ union SMem {
        struct { int wh[NWARP][VOCAB]; } a;                 // phase A
        struct {                                            // phase C
            float  cnt[4][VOCAB];
            float  pooled[4][DD];
            float4 part[16][32];
        } c;
        struct {                                            // phase D
            float  h[4][DD];
            float4 part[16][32];
        } d;
    } sm;

    const int bid = blockIdx.x;
    const int tid = threadIdx.x;

    // ================= PHASE A: half-row histogram =================
    {
        const int warp = tid >> 5;
        const int row  = bid >> 1;
        const int half = bid & 1;
        const int4 xv  = ((const int4*)X)[row * (LL / 4) + half * 512 + tid];
        const int  vl  = vlen[row];
        const int  l0  = half * 2048 + tid * 4;

        for (int i = tid; i < NWARP * VOCAB; i += NT)
            (&sm.a.wh[0][0])[i] = 0;
        __syncthreads();

        if (l0 < vl) {
            atomicAdd(&sm.a.wh[warp][xv.x], 1);
            if (l0 + 1 < vl) atomicAdd(&sm.a.wh[warp][xv.y], 1);
            if (l0 + 2 < vl) atomicAdd(&sm.a.wh[warp][xv.z], 1);
            if (l0 + 3 < vl) atomicAdd(&sm.a.wh[warp][xv.w], 1);
        }
        __syncthreads();

        if (tid < VOCAB) {
            int s = 0;
            #pragma unroll
            for (int w = 0; w < NWARP; w++) s += sm.a.wh[w][tid];
            gpart[bid][tid] = s;                 // zeros naturally if masked out
        }
        __syncthreads();                          // quiesce overlay
    }

    cg::this_grid().sync();

    // tile coordinates shared by phases C and D
    const int r0   = (bid >> 3) * 4;             // 4 rows
    const int c0   = (bid & 7) * 32;             // 32 cols
    const int kg   = tid >> 5;                   // k-group 0..15 (16 k each)
    const int lane = tid & 31;
    const int f4c  = lane & 7;                   // float4 col in tile
    const int rq   = lane >> 3;                  // row in tile
    const int cf4  = (c0 >> 2) + f4c;

    // ================= PHASE C: pooled (on the fly) + layer 1 =================
    {
        // --- prefetch W1 tile into registers (independent of everything) ---
        const float4* W1v = (const float4*)W1;
        float4 w[16];
        #pragma unroll
        for (int j = 0; j < 16; j++)
            w[j] = W1v[(kg * 16 + j) * (DD / 4) + cf4];

        // --- counts for 4 rows ---
        if (tid < 4 * VOCAB) {
            const int r = tid / VOCAB, v = tid % VOCAB;
            sm.c.cnt[r][v] =
                (float)(gpart[(r0 + r) * 2][v] + gpart[(r0 + r) * 2 + 1][v]);
        }
        __syncthreads();

        // --- pooled for 4 rows: thread (d, rh) does rows 2rh, 2rh+1 ---
        {
            const int d  = tid & 255;
            const int rh = tid >> 8;
            float a0 = 0.f, a1 = 0.f;
            #pragma unroll
            for (int v = 0; v < VOCAB; v++) {
                const float m = emb[v * DD + d];          // coalesced, L2-broadcast
                a0 = fmaf(sm.c.cnt[2 * rh + 0][v], m, a0);
                a1 = fmaf(sm.c.cnt[2 * rh + 1][v], m, a1);
            }
            sm.c.pooled[2 * rh + 0][d] = a0;
            sm.c.pooled[2 * rh + 1][d] = a1;
        }
        __syncthreads();

        // --- GEMM from prefetched regs ---
        {
            float4 acc = make_float4(0.f, 0.f, 0.f, 0.f);
            #pragma unroll
            for (int j = 0; j < 16; j++) {
                const float s = sm.c.pooled[rq][kg * 16 + j];
                acc.x = fmaf(s, w[j].x, acc.x);
                acc.y = fmaf(s, w[j].y, acc.y);
                acc.z = fmaf(s, w[j].z, acc.z);
                acc.w = fmaf(s, w[j].w, acc.w);
            }
            sm.c.part[kg][lane] = acc;
        }
        __syncthreads();

        // --- reduce 16 k-groups, bias+relu, store h ---
        if (tid < 128) {
            const int r = tid >> 5, c = tid & 31;
            float s = b1[c0 + c];
            #pragma unroll
            for (int g = 0; g < 16; g++)
                s += ((const float*)&sm.c.part[g][r * 8 + (c >> 2)])[c & 3];
            g_h[(r0 + r) * DD + c0 + c] = fmaxf(s, 0.f);
        }
        __syncthreads();
    }

    cg::this_grid().sync();

    // ================= PHASE D: layer 2 =================
    {
        // --- prefetch W2 tile into registers ---
        const float4* W2v = (const float4*)W2;
        float4 w[16];
        #pragma unroll
        for (int j = 0; j < 16; j++)
            w[j] = W2v[(kg * 16 + j) * (DD / 4) + cf4];

        // --- stage h rows (overlaps W2 latency) ---
        if (tid < 256) {
            const float4 hv = ((const float4*)g_h)[r0 * (DD / 4) + tid];
            ((float4*)&sm.d.h[0][0])[tid] = hv;
        }
        __syncthreads();

        // --- GEMM ---
        {
            float4 acc = make_float4(0.f, 0.f, 0.f, 0.f);
            #pragma unroll
            for (int j = 0; j < 16; j++) {
                const float s = sm.d.h[rq][kg * 16 + j];
                acc.x = fmaf(s, w[j].x, acc.x);
                acc.y = fmaf(s, w[j].y, acc.y);
                acc.z = fmaf(s, w[j].z, acc.z);
                acc.w = fmaf(s, w[j].w, acc.w);
            }
            sm.d.part[kg][lane] = acc;
        }
        __syncthreads();

        // --- reduce, bias+relu, store out ---
        if (tid < 128) {
            const int r = tid >> 5, c = tid & 31;
            float s = b2[c0 + c];
            #pragma unroll
            for (int g = 0; g < 16; g++)
                s += ((const float*)&sm.d.part[g][r * 8 + (c >> 2)])[c & 3];
            out[(r0 + r) * DD + c0 + c] = fmaxf(s, 0.f);
        }
    }
}

extern "C" void kernel_launch(void* const* d_in, const int* in_sizes, int n_in,
                              void* d_out, int out_size)
{
    const int*   X    = (const int*)d_in[0];
    const int*   vlen = (const int*)d_in[1];
    const float* emb  = (const float*)d_in[2];
    const float* W1   = (const float*)d_in[3];
    const float* b1   = (const float*)d_in[4];
    const float* W2   = (const float*)d_in[5];
    const float* b2   = (const float*)d_in[6];
    float*       out  = (float*)d_out;

    void* args[] = { (void*)&X, (void*)&vlen, (void*)&emb, (void*)&W1,
                     (void*)&b1, (void*)&W2, (void*)&b2, (void*)&out };
    cudaLaunchCooperativeKernel((void*)prot_net_coop,
                                dim3(GRID), dim3(NT), args, 0, (cudaStream_t)0);
}